// round 13
// baseline (speedup 1.0000x reference)
#include <cuda_runtime.h>
#include <cstdint>

typedef unsigned long long u64;

// DeformConv3d: B=2, Cin=32, Cout=64, D=8, H=W=48, 3x3x3, s1, p1, d1.
#define CIN     32
#define COUT    64
#define DDIM    8
#define HDIM    48
#define WDIM    48
#define KTAPS   27
#define POSB    128                // positions per block
#define THREADS 256
#define PLANE   (HDIM * WDIM)      // 2304
#define SPATIAL (DDIM * PLANE)     // 18432
#define BATCH   2
#define WTAPU   (CIN * 64)         // 2048 u64 per tap (dup'd pairs)

// dynamic smem layout (bytes)
#define SMV0   0                   // s_v buf0: 16 KB
#define SMV1   16384               // s_v buf1: 16 KB
#define SMW0   32768               // s_wd buf0: 16 KB
#define SMW1   49152               // s_wd buf1: 16 KB
#define SMEMSZ 65536

// channels-last x: g_xT[b][sp][c]
__device__ float g_xT[BATCH * SPATIAL * CIN];
// dup'd weights: g_wd[k][cin][p][ct4][q], u64 = dup(w[co]), co = ct4*4 + p*2 + q
__device__ u64 g_wd[KTAPS * WTAPU];

#define CP_ASYNC16(dst, src) \
    asm volatile("cp.async.ca.shared.global [%0], [%1], 16;" :: "r"(dst), "l"(src))
#define CP_ASYNC_COMMIT()  asm volatile("cp.async.commit_group;" ::: "memory")
#define CP_ASYNC_WAIT0()   asm volatile("cp.async.wait_group 0;" ::: "memory")

__device__ __forceinline__ uint32_t smem_u32(const void* p) {
    uint32_t a;
    asm("{ .reg .u64 t; cvta.to.shared.u64 t, %1; cvt.u32.u64 %0, t; }"
        : "=r"(a) : "l"(p));
    return a;
}

// ---- merged prep: blocks [0,576) transpose x; rest build dup'd weights ----
__global__ __launch_bounds__(256) void prep_kernel(const float* __restrict__ x,
                                                   const float* __restrict__ w) {
    const int t = threadIdx.x;
    if (blockIdx.x < BATCH * (SPATIAL / 64)) {
        __shared__ float s_t[CIN * 65];
        const int blk = blockIdx.x;
        const int b   = blk / (SPATIAL / 64);
        const int sp0 = (blk - b * (SPATIAL / 64)) * 64;
        const float* xb = x + b * (CIN * SPATIAL);
        #pragma unroll
        for (int i = t; i < CIN * 64; i += 256) {
            int c = i >> 6, s = i & 63;
            s_t[c * 65 + s] = xb[c * SPATIAL + sp0 + s];
        }
        __syncthreads();
        float* ob = g_xT + (b * SPATIAL + sp0) * CIN;
        #pragma unroll
        for (int i = t; i < CIN * 64; i += 256) {
            int s = i >> 5, c = i & 31;
            ob[s * CIN + c] = s_t[c * 65 + s];
        }
    } else {
        int i = (blockIdx.x - BATCH * (SPATIAL / 64)) * 256 + t;
        if (i < KTAPS * WTAPU) {
            int k   = i / WTAPU;
            int r   = i - k * WTAPU;
            int cin = r >> 6;
            int m   = r & 63;                 // [p][ct4][q]
            int p   = m >> 5;
            int ct4 = (m >> 1) & 15;
            int q   = m & 1;
            int co  = ct4 * 4 + p * 2 + q;
            float v = w[co * (CIN * KTAPS) + cin * KTAPS + k];
            uint32_t ub = __float_as_uint(v);
            g_wd[i] = ((u64)ub << 32) | ub;
        }
    }
}

// gather one (pos, cq) unit for tap kn
__device__ __forceinline__ void gather_unit(
    int kd, int kh, int kw, int kn, int posl, int dout, int ho, int wo,
    const float* __restrict__ offb, const float* __restrict__ mb,
    const float* __restrict__ xTb, int cq,
    float4 cor[4], float bw[4])
{
    const float oh = offb[(2 * kn) * SPATIAL + posl];
    const float ow = offb[(2 * kn + 1) * SPATIAL + posl];
    const float m  = mb[kn * SPATIAL + posl];

    const int  dp  = kd + dout - 1;
    const bool vdd = (dp >= 0) && (dp < DDIM);
    const int  di  = min(max(dp, 0), DDIM - 1);

    const float h = (float)(kh + ho - 1) + oh;
    const float w = (float)(kw + wo - 1) + ow;
    const float h0f = floorf(h), w0f = floorf(w);
    const float lh = h - h0f, lw = w - w0f;
    const int h0 = (int)h0f, w0 = (int)w0f;
    const int h1 = h0 + 1,   w1 = w0 + 1;

    const bool bh0 = (h0 >= 0) && (h0 < HDIM);
    const bool bh1 = (h1 >= 0) && (h1 < HDIM);
    const bool bw0 = (w0 >= 0) && (w0 < WDIM);
    const bool bw1 = (w1 >= 0) && (w1 < WDIM);

    bw[0] = (1.f - lh) * (1.f - lw) * ((bh0 && bw0 && vdd) ? m : 0.f);
    bw[1] = (1.f - lh) * lw         * ((bh0 && bw1 && vdd) ? m : 0.f);
    bw[2] = lh * (1.f - lw)         * ((bh1 && bw0 && vdd) ? m : 0.f);
    bw[3] = lh * lw                 * ((bh1 && bw1 && vdd) ? m : 0.f);

    const int hc0 = min(max(h0, 0), HDIM - 1);
    const int hc1 = min(max(h1, 0), HDIM - 1);
    const int wc0 = min(max(w0, 0), WDIM - 1);
    const int wc1 = min(max(w1, 0), WDIM - 1);

    const float* base = xTb + (size_t)di * (PLANE * CIN) + cq * 4;
    cor[0] = *(const float4*)(base + (size_t)(hc0 * WDIM + wc0) * CIN);
    cor[1] = *(const float4*)(base + (size_t)(hc0 * WDIM + wc1) * CIN);
    cor[2] = *(const float4*)(base + (size_t)(hc1 * WDIM + wc0) * CIN);
    cor[3] = *(const float4*)(base + (size_t)(hc1 * WDIM + wc1) * CIN);
}

__device__ __forceinline__ float4 combine_unit(const float4 cor[4], const float bw[4]) {
    float4 v;
    v.x = fmaf(bw[0], cor[0].x, fmaf(bw[1], cor[1].x, fmaf(bw[2], cor[2].x, bw[3] * cor[3].x)));
    v.y = fmaf(bw[0], cor[0].y, fmaf(bw[1], cor[1].y, fmaf(bw[2], cor[2].y, bw[3] * cor[3].y)));
    v.z = fmaf(bw[0], cor[0].z, fmaf(bw[1], cor[1].z, fmaf(bw[2], cor[2].z, bw[3] * cor[3].z)));
    v.w = fmaf(bw[0], cor[0].w, fmaf(bw[1], cor[1].w, fmaf(bw[2], cor[2].w, bw[3] * cor[3].w)));
    return v;
}

// GEMM over 16 cin: zero movs — weights arrive as pre-dup'd u64 pairs
__device__ __forceinline__ void gemm_half(
    const float* __restrict__ svp, const u64* __restrict__ swp,
    int c0, int pt, int ct4, u64 acc[4][4])
{
    #pragma unroll
    for (int cin = c0; cin < c0 + 16; cin++) {
        const int s = cin & 28;                       // swizzle (= 4*cq)
        const float4 a0 = *(const float4*)(svp + cin * 128 + ((pt * 8) ^ s));
        const float4 a1 = *(const float4*)(svp + cin * 128 + ((pt * 8 + 4) ^ s));
        const u64 p[4] = {((const u64*)&a0)[0], ((const u64*)&a0)[1],
                          ((const u64*)&a1)[0], ((const u64*)&a1)[1]};
        const ulonglong2 wA = *(const ulonglong2*)(swp + cin * 64 + ct4 * 2);
        const ulonglong2 wB = *(const ulonglong2*)(swp + cin * 64 + 32 + ct4 * 2);
        const u64 wd[4] = {wA.x, wA.y, wB.x, wB.y};   // co = ct4*4 + {0,1,2,3}
        #pragma unroll
        for (int j = 0; j < 4; j++) {
            #pragma unroll
            for (int pp = 0; pp < 4; pp++) {
                asm("fma.rn.f32x2 %0, %1, %2, %0;"
                    : "+l"(acc[pp][j]) : "l"(p[pp]), "l"(wd[j]));
            }
        }
    }
}

__global__ __launch_bounds__(THREADS, 2) void dcn3d_kernel(
    const float* __restrict__ offs,
    const float* __restrict__ mask,
    const float* __restrict__ bias,
    float* __restrict__ out)
{
    extern __shared__ char smc[];
    float* s_v[2]  = {(float*)(smc + SMV0), (float*)(smc + SMV1)};
    u64*   s_wd[2] = {(u64*)(smc + SMW0),  (u64*)(smc + SMW1)};
    const uint32_t swd_a[2] = {smem_u32(smc + SMW0), smem_u32(smc + SMW1)};

    const int t   = threadIdx.x;
    const int cq  = t & 7;                // sampling: channel quad
    const int pa  = t >> 3;               // sampling: pos base (0..31), posl = pa+32u
    const int ct4 = t & 15;               // GEMM: co quad (co = ct4*4 + j)
    const int pt  = t >> 4;               // GEMM: pos octet (pos = pt*8 + i)

    const int blkP = blockIdx.x * POSB;
    const int b    = blkP / SPATIAL;
    const int spb  = blkP - b * SPATIAL;

    const float* offb = offs + b * (2 * KTAPS * SPATIAL) + spb;
    const float* mb   = mask + b * (KTAPS * SPATIAL) + spb;
    const float* xTb  = g_xT + (size_t)b * (SPATIAL * CIN);

    // per-unit spatial decomposition (fixed across taps)
    int dout_u[4], ho_u[4], wo_u[4];
    #pragma unroll
    for (int u = 0; u < 4; u++) {
        const int posl = pa + 32 * u;
        const int sp   = spb + posl;
        const int dd   = sp / PLANE;
        const int r2   = sp - dd * PLANE;
        dout_u[u] = dd;
        ho_u[u]   = r2 / WDIM;
        wo_u[u]   = r2 - (r2 / WDIM) * WDIM;
    }

    float4 sv[4];        // sampled values for current tap

    // ---- prologue: cp.async weights tap0 -> s_wd[0]; sample tap 0 ----
    {
        const char* src = (const char*)g_wd + t * 64;
        const uint32_t dst = swd_a[0] + t * 64;
        #pragma unroll
        for (int i = 0; i < 4; i++) CP_ASYNC16(dst + i * 16, src + i * 16);
        CP_ASYNC_COMMIT();
    }
    {
        float4 cor[4]; float bwc[4];
        #pragma unroll
        for (int u = 0; u < 4; u++) {
            gather_unit(0, 0, 0, 0, pa + 32 * u, dout_u[u], ho_u[u], wo_u[u],
                        offb, mb, xTb, cq, cor, bwc);
            sv[u] = combine_unit(cor, bwc);
        }
    }
    CP_ASYNC_WAIT0();    // own copies of s_wd[0] done (visibility via sync A below)

    u64 acc[4][4];                        // [pospair][co j]
    #pragma unroll
    for (int pp = 0; pp < 4; pp++)
        #pragma unroll
        for (int j = 0; j < 4; j++) acc[pp][j] = 0ULL;

    for (int k = 0; k < KTAPS; k++) {
        const int buf = k & 1;
        const int nb  = buf ^ 1;

        // 1) STS sampled values (swizzled: conflict-free)
        {
            float* svd = s_v[buf];
            #pragma unroll
            for (int u = 0; u < 4; u++) {
                const int px = (pa + 32 * u) ^ (cq * 4);
                const float vv[4] = {sv[u].x, sv[u].y, sv[u].z, sv[u].w};
                #pragma unroll
                for (int c = 0; c < 4; c++)
                    svd[(cq * 4 + c) * 128 + px] = vv[c];
            }
        }

        __syncthreads();   // A: sv(k) + s_wd[buf] (waited last iter) visible to all

        // 2) cp.async weights tap k+1 -> s_wd[nb] (register-free staging)
        {
            const int k2 = min(k + 1, KTAPS - 1);
            const char* src = (const char*)(g_wd + (size_t)k2 * WTAPU) + t * 64;
            const uint32_t dst = swd_a[nb] + t * 64;
            #pragma unroll
            for (int i = 0; i < 4; i++) CP_ASYNC16(dst + i * 16, src + i * 16);
            CP_ASYNC_COMMIT();
        }

        // 3) interleaved: gathers for tap k+1 overlap GEMM of tap k
        const int kn  = min(k + 1, KTAPS - 1);
        const int kd1 = kn / 9;
        const int kh1 = (kn - kd1 * 9) / 3;
        const int kw1 = kn - kd1 * 9 - kh1 * 3;

        const float* svp = s_v[buf];
        const u64*   swp = s_wd[buf];

        {
            float4 corA[4], corB[4]; float bwA[4], bwB[4];
            gather_unit(kd1, kh1, kw1, kn, pa, dout_u[0], ho_u[0], wo_u[0],
                        offb, mb, xTb, cq, corA, bwA);
            gather_unit(kd1, kh1, kw1, kn, pa + 32, dout_u[1], ho_u[1], wo_u[1],
                        offb, mb, xTb, cq, corB, bwB);
            gemm_half(svp, swp, 0, pt, ct4, acc);
            sv[0] = combine_unit(corA, bwA);
            sv[1] = combine_unit(corB, bwB);
        }
        {
            float4 corA[4], corB[4]; float bwA[4], bwB[4];
            gather_unit(kd1, kh1, kw1, kn, pa + 64, dout_u[2], ho_u[2], wo_u[2],
                        offb, mb, xTb, cq, corA, bwA);
            gather_unit(kd1, kh1, kw1, kn, pa + 96, dout_u[3], ho_u[3], wo_u[3],
                        offb, mb, xTb, cq, corB, bwB);
            gemm_half(svp, swp, 16, pt, ct4, acc);
            sv[2] = combine_unit(corA, bwA);
            sv[3] = combine_unit(corB, bwB);
        }

        // 4) wait own cp.async (s_wd[nb]); barrier = WAR guard + cp.async visibility
        CP_ASYNC_WAIT0();
        __syncthreads();   // B
    }

    // ---- epilogue: pos [spb+pt*8, +8), co [ct4*4, +4) ----
    float* ob = out + (size_t)b * (COUT * SPATIAL) + spb + pt * 8;
    #pragma unroll
    for (int j = 0; j < 4; j++) {
        const int co = ct4 * 4 + j;
        const float bv = __ldg(&bias[co]);
        float f[8];
        #pragma unroll
        for (int pp = 0; pp < 4; pp++) {
            asm("mov.b64 {%0, %1}, %2;"
                : "=f"(f[2 * pp]), "=f"(f[2 * pp + 1]) : "l"(acc[pp][j]));
        }
        float4 o0, o1;
        o0.x = f[0] + bv; o0.y = f[1] + bv; o0.z = f[2] + bv; o0.w = f[3] + bv;
        o1.x = f[4] + bv; o1.y = f[5] + bv; o1.z = f[6] + bv; o1.w = f[7] + bv;
        *(float4*)(ob + (size_t)co * SPATIAL)     = o0;
        *(float4*)(ob + (size_t)co * SPATIAL + 4) = o1;
    }
}

extern "C" void kernel_launch(void* const* d_in, const int* in_sizes, int n_in,
                              void* d_out, int out_size)
{
    const float* x    = (const float*)d_in[0];
    const float* offs = (const float*)d_in[1];
    const float* mask = (const float*)d_in[2];
    const float* w    = (const float*)d_in[3];
    const float* bias = (const float*)d_in[4];
    float* out = (float*)d_out;

    cudaFuncSetAttribute(dcn3d_kernel,
                         cudaFuncAttributeMaxDynamicSharedMemorySize, SMEMSZ);

    const int nprep = BATCH * (SPATIAL / 64) + (KTAPS * WTAPU + 255) / 256;
    prep_kernel<<<nprep, 256>>>(x, w);

    const int nblocks = (BATCH * SPATIAL) / POSB;   // 288
    dcn3d_kernel<<<nblocks, THREADS, SMEMSZ>>>(offs, mask, bias, out);
}

// round 14
// speedup vs baseline: 1.5473x; 1.5473x over previous
#include <cuda_runtime.h>
#include <cstdint>

typedef unsigned long long u64;

// DeformConv3d: B=2, Cin=32, Cout=64, D=8, H=W=48, 3x3x3, s1, p1, d1.
#define CIN     32
#define COUT    64
#define DDIM    8
#define HDIM    48
#define WDIM    48
#define KTAPS   27
#define POSB    128                // positions per block
#define THREADS 256
#define PLANE   (HDIM * WDIM)      // 2304
#define SPATIAL (DDIM * PLANE)     // 18432
#define BATCH   2
#define WTAP    (CIN * COUT)       // 2048

// dynamic smem layout (floats): s_v[3][4096] then s_w[2][2048]
#define SV_OFF(i)  ((i) * (CIN * 128))
#define SW_OFF(i)  (3 * (CIN * 128) + (i) * WTAP)
#define SMEMSZ     ((3 * CIN * 128 + 2 * WTAP) * 4)   // 65536 bytes

// channels-last x: g_xT[b][sp][c]
__device__ float g_xT[BATCH * SPATIAL * CIN];
// weights: g_wp[k][cin][co]
__device__ float g_wp[KTAPS * WTAP];

// ---- merged prep: blocks [0,576) transpose x; rest lay out weights ----
__global__ __launch_bounds__(256) void prep_kernel(const float* __restrict__ x,
                                                   const float* __restrict__ w) {
    const int t = threadIdx.x;
    if (blockIdx.x < BATCH * (SPATIAL / 64)) {
        __shared__ float s_t[CIN * 65];
        const int blk = blockIdx.x;
        const int b   = blk / (SPATIAL / 64);
        const int sp0 = (blk - b * (SPATIAL / 64)) * 64;
        const float* xb = x + b * (CIN * SPATIAL);
        #pragma unroll
        for (int i = t; i < CIN * 64; i += 256) {
            int c = i >> 6, s = i & 63;
            s_t[c * 65 + s] = xb[c * SPATIAL + sp0 + s];
        }
        __syncthreads();
        float* ob = g_xT + (b * SPATIAL + sp0) * CIN;
        #pragma unroll
        for (int i = t; i < CIN * 64; i += 256) {
            int s = i >> 5, c = i & 31;
            ob[s * CIN + c] = s_t[c * 65 + s];
        }
    } else {
        int i = (blockIdx.x - BATCH * (SPATIAL / 64)) * 256 + t;
        if (i < KTAPS * WTAP) {
            int k   = i / WTAP;
            int r   = i - k * WTAP;
            int cin = r >> 6;
            int co  = r & 63;
            g_wp[i] = w[co * (CIN * KTAPS) + cin * KTAPS + k];
        }
    }
}

__device__ __forceinline__ u64 dup_f32x2(float v) {
    u64 r;
    asm("mov.b64 %0, {%1, %1};" : "=l"(r) : "f"(v));
    return r;
}

// gather one (pos, cq) unit for tap kn: issue corner loads, compute bilinear coeffs
__device__ __forceinline__ void gather_unit(
    int kd, int kh, int kw, int kn, int posl, int dout, int ho, int wo,
    const float* __restrict__ offb, const float* __restrict__ mb,
    const float* __restrict__ xTb, int cq,
    float4 cor[4], float bw[4])
{
    const float oh = offb[(2 * kn) * SPATIAL + posl];
    const float ow = offb[(2 * kn + 1) * SPATIAL + posl];
    const float m  = mb[kn * SPATIAL + posl];

    const int  dp  = kd + dout - 1;
    const bool vdd = (dp >= 0) && (dp < DDIM);
    const int  di  = min(max(dp, 0), DDIM - 1);

    const float h = (float)(kh + ho - 1) + oh;
    const float w = (float)(kw + wo - 1) + ow;
    const float h0f = floorf(h), w0f = floorf(w);
    const float lh = h - h0f, lw = w - w0f;
    const int h0 = (int)h0f, w0 = (int)w0f;
    const int h1 = h0 + 1,   w1 = w0 + 1;

    const bool bh0 = (h0 >= 0) && (h0 < HDIM);
    const bool bh1 = (h1 >= 0) && (h1 < HDIM);
    const bool bw0 = (w0 >= 0) && (w0 < WDIM);
    const bool bw1 = (w1 >= 0) && (w1 < WDIM);

    bw[0] = (1.f - lh) * (1.f - lw) * ((bh0 && bw0 && vdd) ? m : 0.f);
    bw[1] = (1.f - lh) * lw         * ((bh0 && bw1 && vdd) ? m : 0.f);
    bw[2] = lh * (1.f - lw)         * ((bh1 && bw0 && vdd) ? m : 0.f);
    bw[3] = lh * lw                 * ((bh1 && bw1 && vdd) ? m : 0.f);

    const int hc0 = min(max(h0, 0), HDIM - 1);
    const int hc1 = min(max(h1, 0), HDIM - 1);
    const int wc0 = min(max(w0, 0), WDIM - 1);
    const int wc1 = min(max(w1, 0), WDIM - 1);

    const float* base = xTb + (size_t)di * (PLANE * CIN) + cq * 4;
    cor[0] = *(const float4*)(base + (size_t)(hc0 * WDIM + wc0) * CIN);
    cor[1] = *(const float4*)(base + (size_t)(hc0 * WDIM + wc1) * CIN);
    cor[2] = *(const float4*)(base + (size_t)(hc1 * WDIM + wc0) * CIN);
    cor[3] = *(const float4*)(base + (size_t)(hc1 * WDIM + wc1) * CIN);
}

__device__ __forceinline__ float4 combine_unit(const float4 cor[4], const float bw[4]) {
    float4 v;
    v.x = fmaf(bw[0], cor[0].x, fmaf(bw[1], cor[1].x, fmaf(bw[2], cor[2].x, bw[3] * cor[3].x)));
    v.y = fmaf(bw[0], cor[0].y, fmaf(bw[1], cor[1].y, fmaf(bw[2], cor[2].y, bw[3] * cor[3].y)));
    v.z = fmaf(bw[0], cor[0].z, fmaf(bw[1], cor[1].z, fmaf(bw[2], cor[2].z, bw[3] * cor[3].z)));
    v.w = fmaf(bw[0], cor[0].w, fmaf(bw[1], cor[1].w, fmaf(bw[2], cor[2].w, bw[3] * cor[3].w)));
    return v;
}

__device__ __forceinline__ void gemm_half(
    const float* __restrict__ svp, const float* __restrict__ swp,
    int c0, int pt, int ct4, u64 acc[4][4])
{
    #pragma unroll
    for (int cin = c0; cin < c0 + 16; cin++) {
        const int s = cin & 28;                       // swizzle (= 4*cq)
        const float4 a0 = *(const float4*)(svp + cin * 128 + ((pt * 8) ^ s));
        const float4 a1 = *(const float4*)(svp + cin * 128 + ((pt * 8 + 4) ^ s));
        const u64 p[4] = {((const u64*)&a0)[0], ((const u64*)&a0)[1],
                          ((const u64*)&a1)[0], ((const u64*)&a1)[1]};
        const float4 wq = *(const float4*)(swp + cin * 64 + ct4 * 4);
        const float wj[4] = {wq.x, wq.y, wq.z, wq.w};
        #pragma unroll
        for (int j = 0; j < 4; j++) {
            const u64 wd = dup_f32x2(wj[j]);
            #pragma unroll
            for (int pp = 0; pp < 4; pp++) {
                asm("fma.rn.f32x2 %0, %1, %2, %0;"
                    : "+l"(acc[pp][j]) : "l"(p[pp]), "l"(wd));
            }
        }
    }
}

__global__ __launch_bounds__(THREADS, 2) void dcn3d_kernel(
    const float* __restrict__ offs,
    const float* __restrict__ mask,
    const float* __restrict__ bias,
    float* __restrict__ out)
{
    extern __shared__ float smf[];

    const int t   = threadIdx.x;
    const int cq  = t & 7;                // sampling: channel quad
    const int pa  = t >> 3;               // sampling: pos base (0..31), posl = pa+32u
    const int ct4 = t & 15;               // GEMM: co quad (co = ct4*4 + j)
    const int pt  = t >> 4;               // GEMM: pos octet (pos = pt*8 + i)

    const int blkP = blockIdx.x * POSB;
    const int b    = blkP / SPATIAL;
    const int spb  = blkP - b * SPATIAL;

    const float* offb = offs + b * (2 * KTAPS * SPATIAL) + spb;
    const float* mb   = mask + b * (KTAPS * SPATIAL) + spb;
    const float* xTb  = g_xT + (size_t)b * (SPATIAL * CIN);

    // per-unit spatial decomposition (fixed across taps)
    int dout_u[4], ho_u[4], wo_u[4];
    #pragma unroll
    for (int u = 0; u < 4; u++) {
        const int posl = pa + 32 * u;
        const int sp   = spb + posl;
        const int dd   = sp / PLANE;
        const int r2   = sp - dd * PLANE;
        dout_u[u] = dd;
        ho_u[u]   = r2 / WDIM;
        wo_u[u]   = r2 - (r2 / WDIM) * WDIM;
    }

    float4 sv[4];        // sampled values for current tap
    float4 wreg[2];      // staged weights for tap k+1

    // ---- prologue: weights tap0 -> s_w[0]; weights tap1 -> regs; sample tap0 ----
    {
        const float4* w0 = (const float4*)g_wp;
        ((float4*)(smf + SW_OFF(0)))[t * 2]     = __ldg(w0 + t * 2);
        ((float4*)(smf + SW_OFF(0)))[t * 2 + 1] = __ldg(w0 + t * 2 + 1);
        const float4* w1 = (const float4*)(g_wp + WTAP);
        wreg[0] = __ldg(w1 + t * 2);
        wreg[1] = __ldg(w1 + t * 2 + 1);
    }
    {
        float4 cor[4]; float bwc[4];
        #pragma unroll
        for (int u = 0; u < 4; u++) {
            gather_unit(0, 0, 0, 0, pa + 32 * u, dout_u[u], ho_u[u], wo_u[u],
                        offb, mb, xTb, cq, cor, bwc);
            sv[u] = combine_unit(cor, bwc);
        }
    }

    u64 acc[4][4];                        // [pospair][co j]
    #pragma unroll
    for (int pp = 0; pp < 4; pp++)
        #pragma unroll
        for (int j = 0; j < 4; j++) acc[pp][j] = 0ULL;

    int vb = 0;                           // s_v buffer index (mod-3 rotation)
    for (int k = 0; k < KTAPS; k++) {
        // 1) STS sampled values (swizzled: conflict-free). Reuse distance of
        //    s_v buffers is 3 taps => no WAR barrier needed beyond the one sync.
        {
            float* svd = smf + SV_OFF(vb);
            #pragma unroll
            for (int u = 0; u < 4; u++) {
                const int px = (pa + 32 * u) ^ (cq * 4);
                const float vv[4] = {sv[u].x, sv[u].y, sv[u].z, sv[u].w};
                #pragma unroll
                for (int c = 0; c < 4; c++)
                    svd[(cq * 4 + c) * 128 + px] = vv[c];
            }
        }

        __syncthreads();   // the ONLY barrier per tap: sv(k) + s_w[k&1] visible

        // 2) STS weights for tap k+1 (after sync: GEMM(k-1) readers of this
        //    buffer finished before sync(k) by program order)
        ((float4*)(smf + SW_OFF((k + 1) & 1)))[t * 2]     = wreg[0];
        ((float4*)(smf + SW_OFF((k + 1) & 1)))[t * 2 + 1] = wreg[1];

        // 3) LDG weights tap k+2
        {
            const int k2 = min(k + 2, KTAPS - 1);
            const float4* ws = (const float4*)(g_wp + k2 * WTAP);
            wreg[0] = __ldg(ws + t * 2);
            wreg[1] = __ldg(ws + t * 2 + 1);
        }

        // 4) interleaved: gathers for tap k+1 overlap GEMM of tap k
        const int kn  = min(k + 1, KTAPS - 1);
        const int kd1 = kn / 9;
        const int kh1 = (kn - kd1 * 9) / 3;
        const int kw1 = kn - kd1 * 9 - kh1 * 3;

        const float* svp = smf + SV_OFF(vb);
        const float* swp = smf + SW_OFF(k & 1);

        {
            float4 corA[4], corB[4]; float bwA[4], bwB[4];
            gather_unit(kd1, kh1, kw1, kn, pa, dout_u[0], ho_u[0], wo_u[0],
                        offb, mb, xTb, cq, corA, bwA);
            gather_unit(kd1, kh1, kw1, kn, pa + 32, dout_u[1], ho_u[1], wo_u[1],
                        offb, mb, xTb, cq, corB, bwB);
            gemm_half(svp, swp, 0, pt, ct4, acc);
            sv[0] = combine_unit(corA, bwA);
            sv[1] = combine_unit(corB, bwB);
        }
        {
            float4 corA[4], corB[4]; float bwA[4], bwB[4];
            gather_unit(kd1, kh1, kw1, kn, pa + 64, dout_u[2], ho_u[2], wo_u[2],
                        offb, mb, xTb, cq, corA, bwA);
            gather_unit(kd1, kh1, kw1, kn, pa + 96, dout_u[3], ho_u[3], wo_u[3],
                        offb, mb, xTb, cq, corB, bwB);
            gemm_half(svp, swp, 16, pt, ct4, acc);
            sv[2] = combine_unit(corA, bwA);
            sv[3] = combine_unit(corB, bwB);
        }

        vb = (vb == 2) ? 0 : vb + 1;      // rotate s_v buffer
    }

    // ---- epilogue: pos [spb+pt*8, +8), co [ct4*4, +4) ----
    float* ob = out + (size_t)b * (COUT * SPATIAL) + spb + pt * 8;
    #pragma unroll
    for (int j = 0; j < 4; j++) {
        const int co = ct4 * 4 + j;
        const float bv = __ldg(&bias[co]);
        float f[8];
        #pragma unroll
        for (int pp = 0; pp < 4; pp++) {
            asm("mov.b64 {%0, %1}, %2;"
                : "=f"(f[2 * pp]), "=f"(f[2 * pp + 1]) : "l"(acc[pp][j]));
        }
        float4 o0, o1;
        o0.x = f[0] + bv; o0.y = f[1] + bv; o0.z = f[2] + bv; o0.w = f[3] + bv;
        o1.x = f[4] + bv; o1.y = f[5] + bv; o1.z = f[6] + bv; o1.w = f[7] + bv;
        *(float4*)(ob + (size_t)co * SPATIAL)     = o0;
        *(float4*)(ob + (size_t)co * SPATIAL + 4) = o1;
    }
}

extern "C" void kernel_launch(void* const* d_in, const int* in_sizes, int n_in,
                              void* d_out, int out_size)
{
    const float* x    = (const float*)d_in[0];
    const float* offs = (const float*)d_in[1];
    const float* mask = (const float*)d_in[2];
    const float* w    = (const float*)d_in[3];
    const float* bias = (const float*)d_in[4];
    float* out = (float*)d_out;

    cudaFuncSetAttribute(dcn3d_kernel,
                         cudaFuncAttributeMaxDynamicSharedMemorySize, SMEMSZ);

    const int nprep = BATCH * (SPATIAL / 64) + (KTAPS * WTAP + 255) / 256;
    prep_kernel<<<nprep, 256>>>(x, w);

    const int nblocks = (BATCH * SPATIAL) / POSB;   // 288
    dcn3d_kernel<<<nblocks, THREADS, SMEMSZ>>>(offs, mask, bias, out);
}

// round 17
// speedup vs baseline: 1.5984x; 1.0330x over previous
#include <cuda_runtime.h>
#include <cstdint>

typedef unsigned long long u64;

// DeformConv3d: B=2, Cin=32, Cout=64, D=8, H=W=48, 3x3x3, s1, p1, d1.
#define CIN     32
#define COUT    64
#define DDIM    8
#define HDIM    48
#define WDIM    48
#define KTAPS   27
#define POSB    128                // positions per block
#define THREADS 256
#define PLANE   (HDIM * WDIM)      // 2304
#define SPATIAL (DDIM * PLANE)     // 18432
#define BATCH   2
#define WTAP    (CIN * COUT)       // 2048

// dynamic smem layout (float words):
//   s_v[3][4096] | s_w[2][2048] | s_c[2][ bw float4[128] + off int4[128] ]
#define SV_OFF(i)  ((i) * (CIN * 128))
#define SW_OFF(i)  (3 * CIN * 128 + (i) * WTAP)
#define SCB_OFF(i) (3 * CIN * 128 + 2 * WTAP + (i) * 1024)
#define SCO_OFF(i) (SCB_OFF(i) + 512)
#define SMEMSZ     ((3 * CIN * 128 + 2 * WTAP + 2 * 1024) * 4)   // 73728 B

// channels-last x: g_xT[b][sp][c]
__device__ float g_xT[BATCH * SPATIAL * CIN];
// weights: g_wp[k][cin][co]
__device__ float g_wp[KTAPS * WTAP];

// ---- merged prep: blocks [0,576) transpose x; rest lay out weights ----
__global__ __launch_bounds__(256) void prep_kernel(const float* __restrict__ x,
                                                   const float* __restrict__ w) {
    const int t = threadIdx.x;
    if (blockIdx.x < BATCH * (SPATIAL / 64)) {
        __shared__ float s_t[CIN * 65];
        const int blk = blockIdx.x;
        const int b   = blk / (SPATIAL / 64);
        const int sp0 = (blk - b * (SPATIAL / 64)) * 64;
        const float* xb = x + b * (CIN * SPATIAL);
        #pragma unroll
        for (int i = t; i < CIN * 64; i += 256) {
            int c = i >> 6, s = i & 63;
            s_t[c * 65 + s] = xb[c * SPATIAL + sp0 + s];
        }
        __syncthreads();
        float* ob = g_xT + (b * SPATIAL + sp0) * CIN;
        #pragma unroll
        for (int i = t; i < CIN * 64; i += 256) {
            int s = i >> 5, c = i & 31;
            ob[s * CIN + c] = s_t[c * 65 + s];
        }
    } else {
        int i = (blockIdx.x - BATCH * (SPATIAL / 64)) * 256 + t;
        if (i < KTAPS * WTAP) {
            int k   = i / WTAP;
            int r   = i - k * WTAP;
            int cin = r >> 6;
            int co  = r & 63;
            g_wp[i] = w[co * (CIN * KTAPS) + cin * KTAPS + k];
        }
    }
}

__device__ __forceinline__ u64 dup_f32x2(float v) {
    u64 r;
    asm("mov.b64 %0, {%1, %1};" : "=l"(r) : "f"(v));
    return r;
}

// one thread computes bilinear coeffs + corner word-offsets for one position
__device__ __forceinline__ void coeff_pos(
    int kd, int kh, int kw, int kn, int posl, int dout, int ho, int wo,
    const float* __restrict__ offb, const float* __restrict__ mb,
    float* __restrict__ smf, int cbuf)
{
    const float oh = offb[(2 * kn) * SPATIAL + posl];
    const float ow = offb[(2 * kn + 1) * SPATIAL + posl];
    const float m  = mb[kn * SPATIAL + posl];

    const int  dp  = kd + dout - 1;
    const bool vdd = (dp >= 0) && (dp < DDIM);
    const int  di  = min(max(dp, 0), DDIM - 1);

    const float h = (float)(kh + ho - 1) + oh;
    const float w = (float)(kw + wo - 1) + ow;
    const float h0f = floorf(h), w0f = floorf(w);
    const float lh = h - h0f, lw = w - w0f;
    const int h0 = (int)h0f, w0i = (int)w0f;
    const int h1 = h0 + 1,   w1i = w0i + 1;

    const bool bh0 = (h0  >= 0) && (h0  < HDIM);
    const bool bh1 = (h1  >= 0) && (h1  < HDIM);
    const bool bw0 = (w0i >= 0) && (w0i < WDIM);
    const bool bw1 = (w1i >= 0) && (w1i < WDIM);

    float4 bw4;
    bw4.x = (1.f - lh) * (1.f - lw) * ((bh0 && bw0 && vdd) ? m : 0.f);
    bw4.y = (1.f - lh) * lw         * ((bh0 && bw1 && vdd) ? m : 0.f);
    bw4.z = lh * (1.f - lw)         * ((bh1 && bw0 && vdd) ? m : 0.f);
    bw4.w = lh * lw                 * ((bh1 && bw1 && vdd) ? m : 0.f);

    const int hc0 = min(max(h0, 0),  HDIM - 1);
    const int hc1 = min(max(h1, 0),  HDIM - 1);
    const int wc0 = min(max(w0i, 0), WDIM - 1);
    const int wc1 = min(max(w1i, 0), WDIM - 1);

    const int base = di * (PLANE * CIN);
    int4 of4;
    of4.x = base + (hc0 * WDIM + wc0) * CIN;
    of4.y = base + (hc0 * WDIM + wc1) * CIN;
    of4.z = base + (hc1 * WDIM + wc0) * CIN;
    of4.w = base + (hc1 * WDIM + wc1) * CIN;

    *(float4*)(smf + SCB_OFF(cbuf) + posl * 4) = bw4;
    *(int4*)  (smf + SCO_OFF(cbuf) + posl * 4) = of4;
}

// gather one (pos, cq) unit using precomputed coeffs
__device__ __forceinline__ void gather_issue(
    const float* __restrict__ scb, const int* __restrict__ sco,
    int posl, const float* __restrict__ xq,
    float4& bw, float4 c[4])
{
    bw = *(const float4*)(scb + posl * 4);
    const int4 of = *(const int4*)(sco + posl * 4);
    c[0] = *(const float4*)(xq + of.x);
    c[1] = *(const float4*)(xq + of.y);
    c[2] = *(const float4*)(xq + of.z);
    c[3] = *(const float4*)(xq + of.w);
}

__device__ __forceinline__ float4 combine_unit(const float4 c[4], const float4 bw) {
    float4 v;
    v.x = fmaf(bw.x, c[0].x, fmaf(bw.y, c[1].x, fmaf(bw.z, c[2].x, bw.w * c[3].x)));
    v.y = fmaf(bw.x, c[0].y, fmaf(bw.y, c[1].y, fmaf(bw.z, c[2].y, bw.w * c[3].y)));
    v.z = fmaf(bw.x, c[0].z, fmaf(bw.y, c[1].z, fmaf(bw.z, c[2].z, bw.w * c[3].z)));
    v.w = fmaf(bw.x, c[0].w, fmaf(bw.y, c[1].w, fmaf(bw.z, c[2].w, bw.w * c[3].w)));
    return v;
}

__device__ __forceinline__ void gemm_half(
    const float* __restrict__ svp, const float* __restrict__ swp,
    int c0, int pt, int ct4, u64 acc[4][4])
{
    #pragma unroll
    for (int cin = c0; cin < c0 + 16; cin++) {
        const int s = cin & 28;                       // swizzle (= 4*cq)
        const float4 a0 = *(const float4*)(svp + cin * 128 + ((pt * 8) ^ s));
        const float4 a1 = *(const float4*)(svp + cin * 128 + ((pt * 8 + 4) ^ s));
        const u64 p[4] = {((const u64*)&a0)[0], ((const u64*)&a0)[1],
                          ((const u64*)&a1)[0], ((const u64*)&a1)[1]};
        const float4 wq = *(const float4*)(swp + cin * 64 + ct4 * 4);
        const float wj[4] = {wq.x, wq.y, wq.z, wq.w};
        #pragma unroll
        for (int j = 0; j < 4; j++) {
            const u64 wd = dup_f32x2(wj[j]);
            #pragma unroll
            for (int pp = 0; pp < 4; pp++) {
                asm("fma.rn.f32x2 %0, %1, %2, %0;"
                    : "+l"(acc[pp][j]) : "l"(p[pp]), "l"(wd));
            }
        }
    }
}

__global__ __launch_bounds__(THREADS, 2) void dcn3d_kernel(
    const float* __restrict__ offs,
    const float* __restrict__ mask,
    const float* __restrict__ bias,
    float* __restrict__ out)
{
    extern __shared__ float smf[];

    const int t   = threadIdx.x;
    const int cq  = t & 7;                // sampling: channel quad
    const int pa  = t >> 3;               // sampling: pos base (0..31), posl = pa+32u
    const int ct4 = t & 15;               // GEMM: co quad (co = ct4*4 + j)
    const int pt  = t >> 4;               // GEMM: pos octet (pos = pt*8 + i)

    const int blkP = blockIdx.x * POSB;
    const int b    = blkP / SPATIAL;
    const int spb  = blkP - b * SPATIAL;

    const float* offb = offs + b * (2 * KTAPS * SPATIAL) + spb;
    const float* mb   = mask + b * (KTAPS * SPATIAL) + spb;
    const float* xTb  = g_xT + (size_t)b * (SPATIAL * CIN);
    const float* xq   = xTb + cq * 4;

    // coeff-thread decomposition: thread t<128 owns position t (fixed all taps)
    int dcc = 0, hcc = 0, wcc = 0;
    if (t < 128) {
        const int sp = spb + t;
        dcc = sp / PLANE;
        const int r2 = sp - dcc * PLANE;
        hcc = r2 / WDIM;
        wcc = r2 - (r2 / WDIM) * WDIM;
    }

    float4 sv[4];        // sampled values for current tap
    float4 wreg[2];      // staged weights for tap k+1

    // ---- prologue ----
    if (t < 128) coeff_pos(0, 0, 0, 0, t, dcc, hcc, wcc, offb, mb, smf, 0);
    {
        const float4* w0 = (const float4*)g_wp;
        ((float4*)(smf + SW_OFF(0)))[t * 2]     = __ldg(w0 + t * 2);
        ((float4*)(smf + SW_OFF(0)))[t * 2 + 1] = __ldg(w0 + t * 2 + 1);
        const float4* w1 = (const float4*)(g_wp + WTAP);
        wreg[0] = __ldg(w1 + t * 2);
        wreg[1] = __ldg(w1 + t * 2 + 1);
    }
    __syncthreads();
    {
        const float* scb = smf + SCB_OFF(0);
        const int*   sco = (const int*)(smf + SCO_OFF(0));
        #pragma unroll
        for (int u = 0; u < 4; u++) {
            float4 bw, c[4];
            gather_issue(scb, sco, pa + 32 * u, xq, bw, c);
            sv[u] = combine_unit(c, bw);
        }
    }

    u64 acc[4][4];                        // [pospair][co j]
    #pragma unroll
    for (int pp = 0; pp < 4; pp++)
        #pragma unroll
        for (int j = 0; j < 4; j++) acc[pp][j] = 0ULL;

    int vb = 0;                           // s_v buffer index (mod-3 rotation)
    for (int k = 0; k < KTAPS; k++) {
        const int kn  = min(k + 1, KTAPS - 1);
        const int kd1 = kn / 9;
        const int kh1 = (kn - kd1 * 9) / 3;
        const int kw1 = kn - kd1 * 9 - kh1 * 3;
        const int cb  = kn & 1;

        // 1) STS sampled values (swizzled: conflict-free)
        {
            float* svd = smf + SV_OFF(vb);
            #pragma unroll
            for (int u = 0; u < 4; u++) {
                const int px = (pa + 32 * u) ^ (cq * 4);
                const float vv[4] = {sv[u].x, sv[u].y, sv[u].z, sv[u].w};
                #pragma unroll
                for (int c = 0; c < 4; c++)
                    svd[(cq * 4 + c) * 128 + px] = vv[c];
            }
        }

        // 2) coeffs for tap k+1 (threads < 128 only; shared by all 8 cq)
        if (t < 128)
            coeff_pos(kd1, kh1, kw1, kn, t, dcc, hcc, wcc, offb, mb, smf, cb);

        __syncthreads();   // sv(k), coeffs(k+1), s_w[k&1] all visible

        // 3) STS weights tap k+1; LDG weights tap k+2
        ((float4*)(smf + SW_OFF((k + 1) & 1)))[t * 2]     = wreg[0];
        ((float4*)(smf + SW_OFF((k + 1) & 1)))[t * 2 + 1] = wreg[1];
        {
            const int k2 = min(k + 2, KTAPS - 1);
            const float4* ws = (const float4*)(g_wp + k2 * WTAP);
            wreg[0] = __ldg(ws + t * 2);
            wreg[1] = __ldg(ws + t * 2 + 1);
        }

        // 4) gathers(k+1) overlap GEMM(k)
        const float* svp = smf + SV_OFF(vb);
        const float* swp = smf + SW_OFF(k & 1);
        const float* scb = smf + SCB_OFF(cb);
        const int*   sco = (const int*)(smf + SCO_OFF(cb));

        {
            float4 bwA, bwB, cA[4], cB[4];
            gather_issue(scb, sco, pa,      xq, bwA, cA);
            gather_issue(scb, sco, pa + 32, xq, bwB, cB);
            gemm_half(svp, swp, 0, pt, ct4, acc);
            sv[0] = combine_unit(cA, bwA);
            sv[1] = combine_unit(cB, bwB);
        }
        {
            float4 bwA, bwB, cA[4], cB[4];
            gather_issue(scb, sco, pa + 64, xq, bwA, cA);
            gather_issue(scb, sco, pa + 96, xq, bwB, cB);
            gemm_half(svp, swp, 16, pt, ct4, acc);
            sv[2] = combine_unit(cA, bwA);
            sv[3] = combine_unit(cB, bwB);
        }

        vb = (vb == 2) ? 0 : vb + 1;      // rotate s_v buffer
    }

    // ---- epilogue: pos [spb+pt*8, +8), co [ct4*4, +4) ----
    float* ob = out + (size_t)b * (COUT * SPATIAL) + spb + pt * 8;
    #pragma unroll
    for (int j = 0; j < 4; j++) {
        const int co = ct4 * 4 + j;
        const float bv = __ldg(&bias[co]);
        float f[8];
        #pragma unroll
        for (int pp = 0; pp < 4; pp++) {
            asm("mov.b64 {%0, %1}, %2;"
                : "=f"(f[2 * pp]), "=f"(f[2 * pp + 1]) : "l"(acc[pp][j]));
        }
        float4 o0, o1;
        o0.x = f[0] + bv; o0.y = f[1] + bv; o0.z = f[2] + bv; o0.w = f[3] + bv;
        o1.x = f[4] + bv; o1.y = f[5] + bv; o1.z = f[6] + bv; o1.w = f[7] + bv;
        *(float4*)(ob + (size_t)co * SPATIAL)     = o0;
        *(float4*)(ob + (size_t)co * SPATIAL + 4) = o1;
    }
}

extern "C" void kernel_launch(void* const* d_in, const int* in_sizes, int n_in,
                              void* d_out, int out_size)
{
    const float* x    = (const float*)d_in[0];
    const float* offs = (const float*)d_in[1];
    const float* mask = (const float*)d_in[2];
    const float* w    = (const float*)d_in[3];
    const float* bias = (const float*)d_in[4];
    float* out = (float*)d_out;

    cudaFuncSetAttribute(dcn3d_kernel,
                         cudaFuncAttributeMaxDynamicSharedMemorySize, SMEMSZ);

    const int nprep = BATCH * (SPATIAL / 64) + (KTAPS * WTAP + 255) / 256;
    prep_kernel<<<nprep, 256>>>(x, w);

    const int nblocks = (BATCH * SPATIAL) / POSB;   // 288
    dcn3d_kernel<<<nblocks, THREADS, SMEMSZ>>>(offs, mask, bias, out);
}